// round 15
// baseline (speedup 1.0000x reference)
#include <cuda_runtime.h>
#include <cuda_bf16.h>
#include <math.h>
#include <stdint.h>

#define S    64
#define NF   196608
#define HD   128
#define K2   (2*NF)
#define CL   8

// mma GEMM config
#define G_CTAS 384
#define KPC    512
#define KC     64
#define NCHUNK (KPC/KC)
#define AST    72      // row stride (bf16) for K-chunk=64 tiles

// Scratch (device globals)
__device__ float g_U[S*HD];
__device__ float g_Mt[HD*HD];   // g_Mt[c*HD + h]
__device__ float g_v[HD];
__device__ float g_w0[HD];
__device__ float g_H2[S*HD];    // [t][j]

__device__ __forceinline__ float sigm(float x) { return 1.f / (1.f + expf(-x)); }

// ---- cluster / DSMEM helpers ----
__device__ __forceinline__ uint32_t smem_u32(const void* p) {
    uint32_t a;
    asm("{ .reg .u64 t; cvta.to.shared.u64 t, %1; cvt.u32.u64 %0, t; }" : "=r"(a) : "l"(p));
    return a;
}
__device__ __forceinline__ uint32_t ctarank() {
    uint32_t r; asm("mov.u32 %0, %%cluster_ctarank;" : "=r"(r)); return r;
}
__device__ __forceinline__ uint32_t mapa_u32(uint32_t addr, uint32_t rank) {
    uint32_t r; asm("mapa.shared::cluster.u32 %0, %1, %2;" : "=r"(r) : "r"(addr), "r"(rank));
    return r;
}
__device__ __forceinline__ void st_cluster(uint32_t addr, float v) {
    asm volatile("st.shared::cluster.f32 [%0], %1;" :: "r"(addr), "f"(v) : "memory");
}
#define CLUSTER_BAR() do { \
    asm volatile("barrier.cluster.arrive.aligned;" ::: "memory"); \
    asm volatile("barrier.cluster.wait.aligned;"   ::: "memory"); \
} while (0)
#define CLUSTER_ARRIVE() asm volatile("barrier.cluster.arrive.aligned;" ::: "memory")
#define CLUSTER_WAIT()   asm volatile("barrier.cluster.wait.aligned;"   ::: "memory")

// ---- bf16 split (round-half-up hi, exact residual lo) ----
__device__ __forceinline__ void split_bf2(float2 v, uint32_t& hi, uint32_t& lo) {
    uint32_t bx = __float_as_uint(v.x) + 0x8000u;
    uint32_t by = __float_as_uint(v.y) + 0x8000u;
    float hfx = __uint_as_float(bx & 0xFFFF0000u);
    float hfy = __uint_as_float(by & 0xFFFF0000u);
    hi = __byte_perm(bx, by, 0x7632);
    lo = __byte_perm(__float_as_uint(v.x - hfx), __float_as_uint(v.y - hfy), 0x7632);
}
__device__ __forceinline__ void split_bf1(float x, uint16_t& hi, uint16_t& lo) {
    uint32_t b = __float_as_uint(x) + 0x8000u;
    float hf = __uint_as_float(b & 0xFFFF0000u);
    hi = (uint16_t)(b >> 16);
    lo = (uint16_t)(__float_as_uint(x - hf) >> 16);
}
#define MMA_BF16(c, a, b0_, b1_) \
    asm volatile("mma.sync.aligned.m16n8k16.row.col.f32.bf16.bf16.f32 " \
        "{%0,%1,%2,%3}, {%4,%5,%6,%7}, {%8,%9}, {%0,%1,%2,%3};" \
        : "+f"((c)[0]), "+f"((c)[1]), "+f"((c)[2]), "+f"((c)[3]) \
        : "r"((a)[0]), "r"((a)[1]), "r"((a)[2]), "r"((a)[3]), "r"(b0_), "r"(b1_))
__device__ __forceinline__ void ldsm4(uint32_t* r, uint32_t a) {
    asm volatile("ldmatrix.sync.aligned.m8n8.x4.shared.b16 {%0,%1,%2,%3}, [%4];"
        : "=r"(r[0]), "=r"(r[1]), "=r"(r[2]), "=r"(r[3]) : "r"(a));
}

// ---------------- zero ----------------
__global__ void k_zero() {
    int n = S*HD + HD*HD + 2*HD;
    for (int i = blockIdx.x*blockDim.x + threadIdx.x; i < n; i += gridDim.x*blockDim.x) {
        if (i < S*HD)               g_U[i] = 0.f;
        else if (i < S*HD + HD*HD)  g_Mt[i - S*HD] = 0.f;
        else if (i < S*HD + HD*HD + HD) g_v[i - S*HD - HD*HD] = 0.f;
        else                        g_w0[i - S*HD - HD*HD - HD] = 0.f;
    }
}

// ---------------- fused GEMM (ldmatrix + float4 staging) ----------------
// blocks [0,384) = U (N=64), [384,768) = M (N=128, transposed store to g_Mt).
#define GM_SMEM ((4*128*AST)*2 + 512)
__global__ void __launch_bounds__(256) k_gemm(const float* __restrict__ fc1w,
                                              const float* __restrict__ z,
                                              const float* __restrict__ fc2w,
                                              const float* __restrict__ fc2b,
                                              const float* __restrict__ pg0) {
    extern __shared__ __align__(16) char smem_raw[];
    const int tid = threadIdx.x;
    const int w = tid >> 5, lane = tid & 31;
    const int qr = lane >> 2, qc = lane & 3;
    const int seg = lane >> 3, li = lane & 7;
    // ldmatrix per-lane byte offsets (A: m0=row/k0, m1=row+8/k0, m2=row/k8, m3=row+8/k8;
    //                                 B: m0=n/k0,  m1=n/k8,     m2=n+8/k0, m3=n+8/k8)
    const uint32_t a_lane = (uint32_t)(((16*w + ((seg & 1) << 3) + li) * AST + ((seg >> 1) << 3)) * 2);
    const uint32_t b_lane = (uint32_t)(((((seg >> 1) << 3) + li) * AST + ((seg & 1) << 3)) * 2);

    if (blockIdx.x < G_CTAS) {
        // ======== GEMM U: U[128 x 64] = W_z * Z^T ========
        __nv_bfloat16* Ah = (__nv_bfloat16*)smem_raw;
        __nv_bfloat16* Al = Ah + 128*AST;
        __nv_bfloat16* Bh = Al + 128*AST;
        __nv_bfloat16* Bl = Bh + 64*AST;
        const uint32_t uAh = smem_u32(Ah), uAl = smem_u32(Al);
        const uint32_t uBh = smem_u32(Bh), uBl = smem_u32(Bl);
        float acc[8][4];
        #pragma unroll
        for (int nt = 0; nt < 8; nt++)
            #pragma unroll
            for (int i = 0; i < 4; i++) acc[nt][i] = 0.f;

        const int kbase = blockIdx.x * KPC;
        for (int ch = 0; ch < NCHUNK; ch++) {
            const int kg = kbase + ch*KC;
            __syncthreads();
            #pragma unroll 2
            for (int i = tid; i < 128*16; i += 256) {         // A: float4 staging
                int r = i >> 4, c4 = i & 15;
                float4 v = *(const float4*)(fc1w + r*K2 + kg + 4*c4);
                uint32_t h0, l0, h1, l1;
                split_bf2(make_float2(v.x, v.y), h0, l0);
                split_bf2(make_float2(v.z, v.w), h1, l1);
                *(uint2*)(Ah + r*AST + 4*c4) = make_uint2(h0, h1);
                *(uint2*)(Al + r*AST + 4*c4) = make_uint2(l0, l1);
            }
            #pragma unroll 2
            for (int i = tid; i < 64*16; i += 256) {          // B = z
                int tt = i >> 4, c4 = i & 15;
                float4 v = *(const float4*)(z + tt*NF + kg + 4*c4);
                uint32_t h0, l0, h1, l1;
                split_bf2(make_float2(v.x, v.y), h0, l0);
                split_bf2(make_float2(v.z, v.w), h1, l1);
                *(uint2*)(Bh + tt*AST + 4*c4) = make_uint2(h0, h1);
                *(uint2*)(Bl + tt*AST + 4*c4) = make_uint2(l0, l1);
            }
            __syncthreads();
            #pragma unroll
            for (int ks = 0; ks < 4; ks++) {
                uint32_t ah[4], al[4];
                ldsm4(ah, uAh + a_lane + 32*ks);
                ldsm4(al, uAl + a_lane + 32*ks);
                #pragma unroll
                for (int g = 0; g < 4; g++) {
                    uint32_t bh[4], bl[4];
                    uint32_t bo = b_lane + (uint32_t)(g*(16*AST*2) + 32*ks);
                    ldsm4(bh, uBh + bo);
                    ldsm4(bl, uBl + bo);
                    MMA_BF16(acc[2*g],   ah, bh[0], bh[1]);
                    MMA_BF16(acc[2*g],   ah, bl[0], bl[1]);
                    MMA_BF16(acc[2*g],   al, bh[0], bh[1]);
                    MMA_BF16(acc[2*g+1], ah, bh[2], bh[3]);
                    MMA_BF16(acc[2*g+1], ah, bl[2], bl[3]);
                    MMA_BF16(acc[2*g+1], al, bh[2], bh[3]);
                }
            }
        }
        const int r0 = 16*w + qr;
        #pragma unroll
        for (int nt = 0; nt < 8; nt++) {
            const int t0 = 8*nt + 2*qc;
            atomicAdd(&g_U[t0*HD + r0],         acc[nt][0]);
            atomicAdd(&g_U[(t0+1)*HD + r0],     acc[nt][1]);
            atomicAdd(&g_U[t0*HD + r0 + 8],     acc[nt][2]);
            atomicAdd(&g_U[(t0+1)*HD + r0 + 8], acc[nt][3]);
        }
    } else {
        // ======== GEMM M: Mt (transposed) + side dots ========
        __nv_bfloat16* Ah = (__nv_bfloat16*)smem_raw;
        __nv_bfloat16* Al = Ah + 128*AST;
        __nv_bfloat16* Bh = Al + 128*AST;
        __nv_bfloat16* Bl = Bh + 128*AST;
        float* Es = (float*)(Bl + 128*AST);
        const uint32_t uAh = smem_u32(Ah), uAl = smem_u32(Al);
        const uint32_t uBh = smem_u32(Bh), uBl = smem_u32(Bl);
        const int erow = tid & 127, ewhich = tid >> 7;
        float acc[16][4];
        float accE = 0.f;
        #pragma unroll
        for (int nt = 0; nt < 16; nt++)
            #pragma unroll
            for (int i = 0; i < 4; i++) acc[nt][i] = 0.f;

        const int kbase = (blockIdx.x - G_CTAS) * KPC;
        for (int ch = 0; ch < NCHUNK; ch++) {
            const int kg = kbase + ch*KC;
            __syncthreads();
            #pragma unroll 2
            for (int i = tid; i < 128*16; i += 256) {
                int r = i >> 4, c4 = i & 15;
                float4 v = *(const float4*)(fc1w + r*K2 + NF + kg + 4*c4);
                uint32_t h0, l0, h1, l1;
                split_bf2(make_float2(v.x, v.y), h0, l0);
                split_bf2(make_float2(v.z, v.w), h1, l1);
                *(uint2*)(Ah + r*AST + 4*c4) = make_uint2(h0, h1);
                *(uint2*)(Al + r*AST + 4*c4) = make_uint2(l0, l1);
            }
            #pragma unroll 2
            for (int i = tid; i < 64*32; i += 256) {          // B transpose: float4 over n
                int k = i >> 5, n4 = i & 31;
                float4 v = *(const float4*)(fc2w + (kg + k)*HD + 4*n4);
                int n = 4*n4;
                uint16_t h, l;
                split_bf1(v.x, h, l); *(uint16_t*)&Bh[n*AST + k] = h;     *(uint16_t*)&Bl[n*AST + k] = l;
                split_bf1(v.y, h, l); *(uint16_t*)&Bh[(n+1)*AST + k] = h; *(uint16_t*)&Bl[(n+1)*AST + k] = l;
                split_bf1(v.z, h, l); *(uint16_t*)&Bh[(n+2)*AST + k] = h; *(uint16_t*)&Bl[(n+2)*AST + k] = l;
                split_bf1(v.w, h, l); *(uint16_t*)&Bh[(n+3)*AST + k] = h; *(uint16_t*)&Bl[(n+3)*AST + k] = l;
            }
            if (tid < 128) Es[tid] = (tid < 64) ? fc2b[kg + tid] : pg0[kg + tid - 64];
            __syncthreads();
            #pragma unroll
            for (int ks = 0; ks < 4; ks++) {
                uint32_t ah[4], al[4];
                ldsm4(ah, uAh + a_lane + 32*ks);
                ldsm4(al, uAl + a_lane + 32*ks);
                #pragma unroll
                for (int g = 0; g < 8; g++) {
                    uint32_t bh[4], bl[4];
                    uint32_t bo = b_lane + (uint32_t)(g*(16*AST*2) + 32*ks);
                    ldsm4(bh, uBh + bo);
                    ldsm4(bl, uBl + bo);
                    MMA_BF16(acc[2*g],   ah, bh[0], bh[1]);
                    MMA_BF16(acc[2*g],   ah, bl[0], bl[1]);
                    MMA_BF16(acc[2*g],   al, bh[0], bh[1]);
                    MMA_BF16(acc[2*g+1], ah, bh[2], bh[3]);
                    MMA_BF16(acc[2*g+1], ah, bl[2], bl[3]);
                    MMA_BF16(acc[2*g+1], al, bh[2], bh[3]);
                }
            }
            #pragma unroll 8
            for (int k = 0; k < KC; k++) {
                float a = __bfloat162float(Ah[erow*AST + k]) + __bfloat162float(Al[erow*AST + k]);
                accE += a * Es[ewhich*64 + k];
            }
        }
        const int r0 = 16*w + qr;
        #pragma unroll
        for (int nt = 0; nt < 16; nt++) {
            const int c0 = 8*nt + 2*qc;
            atomicAdd(&g_Mt[c0*HD + r0],         acc[nt][0]);
            atomicAdd(&g_Mt[(c0+1)*HD + r0],     acc[nt][1]);
            atomicAdd(&g_Mt[c0*HD + r0 + 8],     acc[nt][2]);
            atomicAdd(&g_Mt[(c0+1)*HD + r0 + 8], acc[nt][3]);
        }
        atomicAdd(ewhich ? &g_w0[erow] : &g_v[erow], accE);
    }
}

// ---------------- scan v5: local X + arrive/wait-split barriers ----------------
// Wh-dot halves of each LSTM computed in the arrive->wait shadow:
//   window A (h1 broadcast in flight): pd2p = Wh2·h2_{t-1}
//   window B (h2 broadcast in flight): pd1p = Wh1·h1_t (next step) + U prefetch
#define OFS_WI1 0
#define OFS_WH1 8192
#define OFS_WI2 16384
#define OFS_WH2 24576
#define OFS_MT  32768
#define OFS_U   49152
#define OFS_X   49408
#define OFS_XP  49536
#define OFS_H1  49664
#define OFS_H2  49920
#define OFS_G   50176
#define OFS_B1  50240
#define OFS_B2  50304
#define OFS_XB  50368
#define OFS_XB0 50496
#define OFS_C1  50624
#define OFS_C2  50640
#define SCAN_SMEM_FLOATS 50656
#define SCAN_SMEM_BYTES  (SCAN_SMEM_FLOATS*4)

__global__ void __launch_bounds__(256, 1) __cluster_dims__(CL, 1, 1)
k_scan(const float* __restrict__ h1_in, const float* __restrict__ c1_in,
       const float* __restrict__ h2_in, const float* __restrict__ c2_in,
       const float* __restrict__ fc1b,
       const float* __restrict__ wih1, const float* __restrict__ whh1,
       const float* __restrict__ bih1, const float* __restrict__ bhh1,
       const float* __restrict__ wih2, const float* __restrict__ whh2,
       const float* __restrict__ bih2, const float* __restrict__ bhh2,
       float* __restrict__ out, int out_size)
{
    extern __shared__ __align__(16) float sm[];
    const int tid  = threadIdx.x;
    const int warp = tid >> 5, lane = tid & 31;
    const uint32_t rank = ctarank();
    const uint32_t sbase = smem_u32(sm);

    for (int idx = tid; idx < 64*128; idx += 256) {
        int l = idx >> 7, k = idx & 127;
        int gr = ((l >> 4) << 7) + (int)rank*16 + (l & 15);
        sm[OFS_WI1 + idx] = wih1[gr*HD + k];
        sm[OFS_WH1 + idx] = whh1[gr*HD + k];
        sm[OFS_WI2 + idx] = wih2[gr*HD + k];
        sm[OFS_WH2 + idx] = whh2[gr*HD + k];
    }
    for (int idx = tid; idx < HD*HD; idx += 256) sm[OFS_MT + idx] = g_Mt[idx];
    if (tid < 64) {
        int gr = ((tid >> 4) << 7) + (int)rank*16 + (tid & 15);
        sm[OFS_B1 + tid] = bih1[gr] + bhh1[gr];
        sm[OFS_B2 + tid] = bih2[gr] + bhh2[gr];
    }
    if (tid < HD) {
        sm[OFS_XB  + tid] = fc1b[tid] + g_v[tid];
        sm[OFS_XB0 + tid] = fc1b[tid] + g_w0[tid];
        sm[OFS_U   + tid] = g_U[tid];
        sm[OFS_H1 + HD + tid] = h1_in[tid];
        sm[OFS_H2 + HD + tid] = h2_in[tid];
    }
    if (tid < 16) {
        int e = (int)rank*16 + tid;
        sm[OFS_C1 + tid] = c1_in[e];
        sm[OFS_C2 + tid] = c2_in[e];
    }
    __syncthreads();
    CLUSTER_BAR();

    float pd1p[8], pd2p[8];
    {   // pd1p for t=0: Wh1 · h1_init (buffer 1)
        float4 hv = ((const float4*)(sm + OFS_H1 + HD))[lane];
        #pragma unroll
        for (int i = 0; i < 8; i++) {
            int l = warp*8 + i;
            float4 wh = ((const float4*)(sm + OFS_WH1 + l*HD))[lane];
            pd1p[i] = wh.x*hv.x + wh.y*hv.y + wh.z*hv.z + wh.w*hv.w;
        }
    }

    for (int t = 0; t < S; t++) {
        const int p = t & 1;

        // ---- X phase (local) ----
        if (t == 0) {
            if (tid < HD) sm[OFS_X + tid] = fmaxf(sm[OFS_U + tid] + sm[OFS_XB0 + tid], 0.f);
            __syncthreads();
        } else {
            const int half = tid >> 7, h = tid & 127;
            const float* mt = sm + OFS_MT + half*64*HD;
            const float* hv = sm + OFS_H2 + (p^1)*HD + half*64;
            float a = 0.f;
            #pragma unroll 16
            for (int c = 0; c < 64; c++) a = fmaf(mt[c*HD + h], hv[c], a);
            sm[(half ? OFS_XP : OFS_X) + h] = a;
            __syncthreads();
            if (tid < HD)
                sm[OFS_X + tid] = fmaxf(sm[OFS_X + tid] + sm[OFS_XP + tid]
                                        + sm[OFS_U + p*HD + tid] + sm[OFS_XB + tid], 0.f);
            __syncthreads();
        }

        // ---- LSTM1: Wi1·x + precomputed Wh1·h1_{t-1} ----
        {
            float4 xv = ((const float4*)(sm + OFS_X))[lane];
            #pragma unroll
            for (int i = 0; i < 8; i++) {
                int l = warp*8 + i;
                float4 wi = ((const float4*)(sm + OFS_WI1 + l*HD))[lane];
                float pd = wi.x*xv.x + wi.y*xv.y + wi.z*xv.z + wi.w*xv.w + pd1p[i];
                #pragma unroll
                for (int off = 16; off; off >>= 1) pd += __shfl_xor_sync(0xffffffffu, pd, off);
                if (lane == 0) sm[OFS_G + l] = pd + sm[OFS_B1 + l];
            }
        }
        __syncthreads();
        if (tid < 16) {
            float gi = sm[OFS_G + tid],      gf = sm[OFS_G + 16 + tid];
            float gg = sm[OFS_G + 32 + tid], go = sm[OFS_G + 48 + tid];
            float c = sigm(gf)*sm[OFS_C1 + tid] + sigm(gi)*tanhf(gg);
            sm[OFS_C1 + tid] = c;
            sm[OFS_H1 + p*HD + (int)rank*16 + tid] = sigm(go)*tanhf(c);
        }
        __syncthreads();
        if (tid < 128) {
            int e = (int)rank*16 + (tid >> 3);
            st_cluster(mapa_u32(sbase + (uint32_t)(OFS_H1 + p*HD + e)*4u, (uint32_t)(tid & 7)),
                       sm[OFS_H1 + p*HD + e]);
        }
        CLUSTER_ARRIVE();
        {   // window A: pd2p = Wh2 · h2_{t-1}  (buffer p^1, local)
            float4 hv = ((const float4*)(sm + OFS_H2 + (p^1)*HD))[lane];
            #pragma unroll
            for (int i = 0; i < 8; i++) {
                int l = warp*8 + i;
                float4 wh = ((const float4*)(sm + OFS_WH2 + l*HD))[lane];
                pd2p[i] = wh.x*hv.x + wh.y*hv.y + wh.z*hv.z + wh.w*hv.w;
            }
        }
        CLUSTER_WAIT();   // h1_t full delivered

        // ---- LSTM2: Wi2·h1_t + pd2p ----
        {
            float4 xv = ((const float4*)(sm + OFS_H1 + p*HD))[lane];
            #pragma unroll
            for (int i = 0; i < 8; i++) {
                int l = warp*8 + i;
                float4 wi = ((const float4*)(sm + OFS_WI2 + l*HD))[lane];
                float pd = wi.x*xv.x + wi.y*xv.y + wi.z*xv.z + wi.w*xv.w + pd2p[i];
                #pragma unroll
                for (int off = 16; off; off >>= 1) pd += __shfl_xor_sync(0xffffffffu, pd, off);
                if (lane == 0) sm[OFS_G + l] = pd + sm[OFS_B2 + l];
            }
        }
        __syncthreads();
        if (tid < 16) {
            float gi = sm[OFS_G + tid],      gf = sm[OFS_G + 16 + tid];
            float gg = sm[OFS_G + 32 + tid], go = sm[OFS_G + 48 + tid];
            float c = sigm(gf)*sm[OFS_C2 + tid] + sigm(gi)*tanhf(gg);
            sm[OFS_C2 + tid] = c;
            float h = sigm(go)*tanhf(c);
            int e = (int)rank*16 + tid;
            sm[OFS_H2 + p*HD + e] = h;
            g_H2[t*HD + e] = h;
        }
        __syncthreads();
        if (tid < 128) {
            int e = (int)rank*16 + (tid >> 3);
            st_cluster(mapa_u32(sbase + (uint32_t)(OFS_H2 + p*HD + e)*4u, (uint32_t)(tid & 7)),
                       sm[OFS_H2 + p*HD + e]);
        }
        CLUSTER_ARRIVE();
        {   // window B: pd1p(next) = Wh1 · h1_t (buffer p, local); U prefetch
            float4 hv = ((const float4*)(sm + OFS_H1 + p*HD))[lane];
            #pragma unroll
            for (int i = 0; i < 8; i++) {
                int l = warp*8 + i;
                float4 wh = ((const float4*)(sm + OFS_WH1 + l*HD))[lane];
                pd1p[i] = wh.x*hv.x + wh.y*hv.y + wh.z*hv.z + wh.w*hv.w;
            }
            if (t < S-1 && tid < HD) sm[OFS_U + (p^1)*HD + tid] = g_U[(t+1)*HD + tid];
        }
        CLUSTER_WAIT();   // h2_t full delivered
    }

    if (out_size >= S*NF + 4*HD && tid < 16) {
        int e = (int)rank*16 + tid;
        out[S*NF + 0*HD + e] = sm[OFS_H1 + HD + e];
        out[S*NF + 1*HD + e] = sm[OFS_C1 + tid];
        out[S*NF + 2*HD + e] = sm[OFS_H2 + HD + e];
        out[S*NF + 3*HD + e] = sm[OFS_C2 + tid];
    }
}

// ---------------- k_out v2 (R13 verbatim) ----------------
#define KO_SMEM ((2*128*AST + 2*64*AST)*2 + 512)
__global__ void __launch_bounds__(256, 4) k_out(const float* __restrict__ fc2w,
                                                const float* __restrict__ fc2b,
                                                const float* __restrict__ y,
                                                float* __restrict__ out) {
    extern __shared__ __align__(16) char smem_raw[];
    __nv_bfloat16* Ah = (__nv_bfloat16*)smem_raw;
    __nv_bfloat16* Al = Ah + 128*AST;
    __nv_bfloat16* Bh = Al + 128*AST;
    __nv_bfloat16* Bl = Bh + 64*AST;
    float* bs = (float*)(Bl + 64*AST);
    float* Cs = (float*)smem_raw;
    const int tid = threadIdx.x;
    const int w = tid >> 5, lane = tid & 31;
    const int qr = lane >> 2, qc = lane & 3;
    const int kg = blockIdx.x * 128;

    float acc[8][4];
    #pragma unroll
    for (int nt = 0; nt < 8; nt++)
        #pragma unroll
        for (int i = 0; i < 4; i++) acc[nt][i] = 0.f;

    if (tid < 128) bs[tid] = fc2b[kg + tid];

    for (int ck = 0; ck < 2; ck++) {
        const int ko = ck*64;
        __syncthreads();
        for (int i = tid; i < 128*32; i += 256) {
            int r = i >> 5, c2 = i & 31;
            float2 v = *(const float2*)(fc2w + (kg + r)*HD + ko + 2*c2);
            uint32_t h, l; split_bf2(v, h, l);
            *(uint32_t*)(Ah + r*AST + 2*c2) = h;
            *(uint32_t*)(Al + r*AST + 2*c2) = l;
        }
        for (int i = tid; i < 64*32; i += 256) {
            int tt = i >> 5, c2 = i & 31;
            float2 v = *(const float2*)(g_H2 + tt*HD + ko + 2*c2);
            uint32_t h, l; split_bf2(v, h, l);
            *(uint32_t*)(Bh + tt*AST + 2*c2) = h;
            *(uint32_t*)(Bl + tt*AST + 2*c2) = l;
        }
        __syncthreads();
        #pragma unroll
        for (int ks = 0; ks < 4; ks++) {
            const int kk = ks*16;
            const int r0 = 16*w + qr;
            uint32_t ah[4], al[4];
            ah[0] = *(const uint32_t*)(Ah + r0*AST + kk + 2*qc);
            ah[1] = *(const uint32_t*)(Ah + (r0+8)*AST + kk + 2*qc);
            ah[2] = *(const uint32_t*)(Ah + r0*AST + kk + 2*qc + 8);
            ah[3] = *(const uint32_t*)(Ah + (r0+8)*AST + kk + 2*qc + 8);
            al[0] = *(const uint32_t*)(Al + r0*AST + kk + 2*qc);
            al[1] = *(const uint32_t*)(Al + (r0+8)*AST + kk + 2*qc);
            al[2] = *(const uint32_t*)(Al + r0*AST + kk + 2*qc + 8);
            al[3] = *(const uint32_t*)(Al + (r0+8)*AST + kk + 2*qc + 8);
            #pragma unroll
            for (int nt = 0; nt < 8; nt++) {
                const int cn = 8*nt + qr;
                uint32_t bh0 = *(const uint32_t*)(Bh + cn*AST + kk + 2*qc);
                uint32_t bh1 = *(const uint32_t*)(Bh + cn*AST + kk + 2*qc + 8);
                uint32_t bl0 = *(const uint32_t*)(Bl + cn*AST + kk + 2*qc);
                uint32_t bl1 = *(const uint32_t*)(Bl + cn*AST + kk + 2*qc + 8);
                MMA_BF16(acc[nt], ah, bh0, bh1);
                MMA_BF16(acc[nt], ah, bl0, bl1);
                MMA_BF16(acc[nt], al, bh0, bh1);
            }
        }
    }
    __syncthreads();

    {
        const int r0 = 16*w + qr;
        #pragma unroll
        for (int nt = 0; nt < 8; nt++) {
            const int t0 = 8*nt + 2*qc;
            Cs[t0*132 + r0]           = acc[nt][0];
            Cs[(t0+1)*132 + r0]       = acc[nt][1];
            Cs[t0*132 + r0 + 8]       = acc[nt][2];
            Cs[(t0+1)*132 + r0 + 8]   = acc[nt][3];
        }
    }
    __syncthreads();

    for (int i = tid; i < 64*128; i += 256) {
        int tt = i >> 7, kk = i & 127;
        out[tt*NF + kg + kk] = Cs[tt*132 + kk] + bs[kk] + y[tt*NF + kg + kk];
    }
}

// ---------------- launcher ----------------
extern "C" void kernel_launch(void* const* d_in, const int* in_sizes, int n_in,
                              void* d_out, int out_size) {
    const float* z    = (const float*)d_in[0];
    const float* y    = (const float*)d_in[1];
    const float* pg0  = (const float*)d_in[2];
    const float* h1   = (const float*)d_in[3];
    const float* c1   = (const float*)d_in[4];
    const float* h2   = (const float*)d_in[5];
    const float* c2   = (const float*)d_in[6];
    const float* fc1w = (const float*)d_in[7];
    const float* fc1b = (const float*)d_in[8];
    const float* wih1 = (const float*)d_in[9];
    const float* whh1 = (const float*)d_in[10];
    const float* bih1 = (const float*)d_in[11];
    const float* bhh1 = (const float*)d_in[12];
    const float* wih2 = (const float*)d_in[13];
    const float* whh2 = (const float*)d_in[14];
    const float* bih2 = (const float*)d_in[15];
    const float* bhh2 = (const float*)d_in[16];
    const float* fc2w = (const float*)d_in[17];
    const float* fc2b = (const float*)d_in[18];
    float* out = (float*)d_out;

    cudaFuncSetAttribute(k_scan, cudaFuncAttributeMaxDynamicSharedMemorySize, SCAN_SMEM_BYTES);
    cudaFuncSetAttribute(k_gemm, cudaFuncAttributeMaxDynamicSharedMemorySize, GM_SMEM);
    cudaFuncSetAttribute(k_out,  cudaFuncAttributeMaxDynamicSharedMemorySize, KO_SMEM);

    k_zero<<<32, 256>>>();
    k_gemm<<<2*G_CTAS, 256, GM_SMEM>>>(fc1w, z, fc2w, fc2b, pg0);
    k_scan<<<CL, 256, SCAN_SMEM_BYTES>>>(h1, c1, h2, c2, fc1b,
                                         wih1, whh1, bih1, bhh1,
                                         wih2, whh2, bih2, bhh2,
                                         out, out_size);
    k_out<<<NF/128, 256, KO_SMEM>>>(fc2w, fc2b, y, out);
}

// round 16
// speedup vs baseline: 1.0923x; 1.0923x over previous
#include <cuda_runtime.h>
#include <cuda_bf16.h>
#include <math.h>
#include <stdint.h>

#define S    64
#define NF   196608
#define HD   128
#define K2   (2*NF)
#define CL   8

// mma GEMM config
#define G_CTAS 384
#define KPC    512
#define KC     64
#define NCHUNK (KPC/KC)
#define AST    72      // row stride (bf16) for K-chunk=64 tiles

// scan launch: cluster 0 scans, clusters 1..36 prefetch fc2w into L2
#define SCAN_GRID 296

// Scratch (device globals)
__device__ float g_U[S*HD];
__device__ float g_Mt[HD*HD];   // g_Mt[c*HD + h]
__device__ float g_v[HD];
__device__ float g_w0[HD];
__device__ float g_H2[S*HD];    // [t][j]
__device__ float g_sink;        // DCE-defeat for the L2 prefetch

__device__ __forceinline__ float sigm(float x) { return 1.f / (1.f + expf(-x)); }

// ---- cluster / DSMEM helpers ----
__device__ __forceinline__ uint32_t smem_u32(const void* p) {
    uint32_t a;
    asm("{ .reg .u64 t; cvta.to.shared.u64 t, %1; cvt.u32.u64 %0, t; }" : "=r"(a) : "l"(p));
    return a;
}
__device__ __forceinline__ uint32_t ctarank() {
    uint32_t r; asm("mov.u32 %0, %%cluster_ctarank;" : "=r"(r)); return r;
}
__device__ __forceinline__ uint32_t mapa_u32(uint32_t addr, uint32_t rank) {
    uint32_t r; asm("mapa.shared::cluster.u32 %0, %1, %2;" : "=r"(r) : "r"(addr), "r"(rank));
    return r;
}
__device__ __forceinline__ void st_cluster(uint32_t addr, float v) {
    asm volatile("st.shared::cluster.f32 [%0], %1;" :: "r"(addr), "f"(v) : "memory");
}
#define CLUSTER_BAR() do { \
    asm volatile("barrier.cluster.arrive.aligned;" ::: "memory"); \
    asm volatile("barrier.cluster.wait.aligned;"   ::: "memory"); \
} while (0)

// ---- bf16 split (round-half-up hi, exact residual lo) ----
__device__ __forceinline__ void split_bf2(float2 v, uint32_t& hi, uint32_t& lo) {
    uint32_t bx = __float_as_uint(v.x) + 0x8000u;
    uint32_t by = __float_as_uint(v.y) + 0x8000u;
    float hfx = __uint_as_float(bx & 0xFFFF0000u);
    float hfy = __uint_as_float(by & 0xFFFF0000u);
    hi = __byte_perm(bx, by, 0x7632);
    lo = __byte_perm(__float_as_uint(v.x - hfx), __float_as_uint(v.y - hfy), 0x7632);
}
__device__ __forceinline__ void split_bf1(float x, uint16_t& hi, uint16_t& lo) {
    uint32_t b = __float_as_uint(x) + 0x8000u;
    float hf = __uint_as_float(b & 0xFFFF0000u);
    hi = (uint16_t)(b >> 16);
    lo = (uint16_t)(__float_as_uint(x - hf) >> 16);
}
#define MMA_BF16(c, a, b0_, b1_) \
    asm volatile("mma.sync.aligned.m16n8k16.row.col.f32.bf16.bf16.f32 " \
        "{%0,%1,%2,%3}, {%4,%5,%6,%7}, {%8,%9}, {%0,%1,%2,%3};" \
        : "+f"((c)[0]), "+f"((c)[1]), "+f"((c)[2]), "+f"((c)[3]) \
        : "r"((a)[0]), "r"((a)[1]), "r"((a)[2]), "r"((a)[3]), "r"(b0_), "r"(b1_))

// ---------------- zero ----------------
__global__ void k_zero() {
    int n = S*HD + HD*HD + 2*HD;
    for (int i = blockIdx.x*blockDim.x + threadIdx.x; i < n; i += gridDim.x*blockDim.x) {
        if (i < S*HD)               g_U[i] = 0.f;
        else if (i < S*HD + HD*HD)  g_Mt[i - S*HD] = 0.f;
        else if (i < S*HD + HD*HD + HD) g_v[i - S*HD - HD*HD] = 0.f;
        else                        g_w0[i - S*HD - HD*HD - HD] = 0.f;
    }
}

// ---------------- fused GEMM with register-prefetch pipeline (R13 verbatim) ----------------
#define GM_SMEM ((4*128*AST)*2 + 512)
__global__ void __launch_bounds__(256) k_gemm(const float* __restrict__ fc1w,
                                              const float* __restrict__ z,
                                              const float* __restrict__ fc2w,
                                              const float* __restrict__ fc2b,
                                              const float* __restrict__ pg0) {
    extern __shared__ __align__(16) char smem_raw[];
    const int tid = threadIdx.x;
    const int w = tid >> 5, lane = tid & 31;
    const int qr = lane >> 2, qc = lane & 3;

    if (blockIdx.x < G_CTAS) {
        // ======== GEMM U: U[128 x 64] = W_z * Z^T ========
        __nv_bfloat16* Ah = (__nv_bfloat16*)smem_raw;
        __nv_bfloat16* Al = Ah + 128*AST;
        __nv_bfloat16* Bh = Al + 128*AST;
        __nv_bfloat16* Bl = Bh + 64*AST;
        float acc[8][4];
        #pragma unroll
        for (int nt = 0; nt < 8; nt++)
            #pragma unroll
            for (int i = 0; i < 4; i++) acc[nt][i] = 0.f;

        float2 pa[16], pb[8];
        const int kbase = blockIdx.x * KPC;

        #pragma unroll
        for (int j = 0; j < 16; j++) {
            int i = tid + j*256, r = i >> 5, c2 = i & 31;
            pa[j] = *(const float2*)(fc1w + r*K2 + kbase + 2*c2);
        }
        #pragma unroll
        for (int j = 0; j < 8; j++) {
            int i = tid + j*256, tt = i >> 5, c2 = i & 31;
            pb[j] = *(const float2*)(z + tt*NF + kbase + 2*c2);
        }

        for (int ch = 0; ch < NCHUNK; ch++) {
            const int kgn = kbase + (ch+1)*KC;
            __syncthreads();
            #pragma unroll
            for (int j = 0; j < 16; j++) {
                int i = tid + j*256, r = i >> 5, c2 = i & 31;
                uint32_t h, l; split_bf2(pa[j], h, l);
                *(uint32_t*)(Ah + r*AST + 2*c2) = h;
                *(uint32_t*)(Al + r*AST + 2*c2) = l;
            }
            #pragma unroll
            for (int j = 0; j < 8; j++) {
                int i = tid + j*256, tt = i >> 5, c2 = i & 31;
                uint32_t h, l; split_bf2(pb[j], h, l);
                *(uint32_t*)(Bh + tt*AST + 2*c2) = h;
                *(uint32_t*)(Bl + tt*AST + 2*c2) = l;
            }
            __syncthreads();
            if (ch + 1 < NCHUNK) {
                #pragma unroll
                for (int j = 0; j < 16; j++) {
                    int i = tid + j*256, r = i >> 5, c2 = i & 31;
                    pa[j] = *(const float2*)(fc1w + r*K2 + kgn + 2*c2);
                }
                #pragma unroll
                for (int j = 0; j < 8; j++) {
                    int i = tid + j*256, tt = i >> 5, c2 = i & 31;
                    pb[j] = *(const float2*)(z + tt*NF + kgn + 2*c2);
                }
            }
            #pragma unroll
            for (int ks = 0; ks < 4; ks++) {
                const int kk = ks*16;
                const int r0 = 16*w + qr;
                uint32_t ah[4], al[4];
                ah[0] = *(const uint32_t*)(Ah + r0*AST + kk + 2*qc);
                ah[1] = *(const uint32_t*)(Ah + (r0+8)*AST + kk + 2*qc);
                ah[2] = *(const uint32_t*)(Ah + r0*AST + kk + 2*qc + 8);
                ah[3] = *(const uint32_t*)(Ah + (r0+8)*AST + kk + 2*qc + 8);
                al[0] = *(const uint32_t*)(Al + r0*AST + kk + 2*qc);
                al[1] = *(const uint32_t*)(Al + (r0+8)*AST + kk + 2*qc);
                al[2] = *(const uint32_t*)(Al + r0*AST + kk + 2*qc + 8);
                al[3] = *(const uint32_t*)(Al + (r0+8)*AST + kk + 2*qc + 8);
                #pragma unroll
                for (int nt = 0; nt < 8; nt++) {
                    const int cn = 8*nt + qr;
                    uint32_t bh0 = *(const uint32_t*)(Bh + cn*AST + kk + 2*qc);
                    uint32_t bh1 = *(const uint32_t*)(Bh + cn*AST + kk + 2*qc + 8);
                    uint32_t bl0 = *(const uint32_t*)(Bl + cn*AST + kk + 2*qc);
                    uint32_t bl1 = *(const uint32_t*)(Bl + cn*AST + kk + 2*qc + 8);
                    MMA_BF16(acc[nt], ah, bh0, bh1);
                    MMA_BF16(acc[nt], ah, bl0, bl1);
                    MMA_BF16(acc[nt], al, bh0, bh1);
                }
            }
        }
        const int r0 = 16*w + qr;
        #pragma unroll
        for (int nt = 0; nt < 8; nt++) {
            const int t0 = 8*nt + 2*qc;
            atomicAdd(&g_U[t0*HD + r0],         acc[nt][0]);
            atomicAdd(&g_U[(t0+1)*HD + r0],     acc[nt][1]);
            atomicAdd(&g_U[t0*HD + r0 + 8],     acc[nt][2]);
            atomicAdd(&g_U[(t0+1)*HD + r0 + 8], acc[nt][3]);
        }
    } else {
        // ======== GEMM M: Mt (transposed store) + side dots; A prefetched ========
        __nv_bfloat16* Ah = (__nv_bfloat16*)smem_raw;
        __nv_bfloat16* Al = Ah + 128*AST;
        __nv_bfloat16* Bh = Al + 128*AST;
        __nv_bfloat16* Bl = Bh + 128*AST;
        float* Es = (float*)(Bl + 128*AST);
        const int erow = tid & 127, ewhich = tid >> 7;
        float acc[16][4];
        float accE = 0.f;
        #pragma unroll
        for (int nt = 0; nt < 16; nt++)
            #pragma unroll
            for (int i = 0; i < 4; i++) acc[nt][i] = 0.f;

        float2 pa[16];
        const int kbase = (blockIdx.x - G_CTAS) * KPC;
        #pragma unroll
        for (int j = 0; j < 16; j++) {
            int i = tid + j*256, r = i >> 5, c2 = i & 31;
            pa[j] = *(const float2*)(fc1w + r*K2 + NF + kbase + 2*c2);
        }

        for (int ch = 0; ch < NCHUNK; ch++) {
            const int kg = kbase + ch*KC;
            __syncthreads();
            #pragma unroll
            for (int j = 0; j < 16; j++) {
                int i = tid + j*256, r = i >> 5, c2 = i & 31;
                uint32_t h, l; split_bf2(pa[j], h, l);
                *(uint32_t*)(Ah + r*AST + 2*c2) = h;
                *(uint32_t*)(Al + r*AST + 2*c2) = l;
            }
            #pragma unroll 4
            for (int j = 0; j < 16; j++) {
                int i = tid + j*256, k = i >> 6, n2 = i & 63, n = 2*n2;
                float2 v = *(const float2*)(fc2w + (kg + k)*HD + n);
                uint32_t h, l; split_bf2(v, h, l);
                Bh[n*AST + k]     = __ushort_as_bfloat16((uint16_t)(h & 0xffffu));
                Bh[(n+1)*AST + k] = __ushort_as_bfloat16((uint16_t)(h >> 16));
                Bl[n*AST + k]     = __ushort_as_bfloat16((uint16_t)(l & 0xffffu));
                Bl[(n+1)*AST + k] = __ushort_as_bfloat16((uint16_t)(l >> 16));
            }
            if (tid < 128) Es[tid] = (tid < 64) ? fc2b[kg + tid] : pg0[kg + tid - 64];
            __syncthreads();
            if (ch + 1 < NCHUNK) {
                #pragma unroll
                for (int j = 0; j < 16; j++) {
                    int i = tid + j*256, r = i >> 5, c2 = i & 31;
                    pa[j] = *(const float2*)(fc1w + r*K2 + NF + kg + KC + 2*c2);
                }
            }
            #pragma unroll
            for (int ks = 0; ks < 4; ks++) {
                const int kk = ks*16;
                const int r0 = 16*w + qr;
                uint32_t ah[4], al[4];
                ah[0] = *(const uint32_t*)(Ah + r0*AST + kk + 2*qc);
                ah[1] = *(const uint32_t*)(Ah + (r0+8)*AST + kk + 2*qc);
                ah[2] = *(const uint32_t*)(Ah + r0*AST + kk + 2*qc + 8);
                ah[3] = *(const uint32_t*)(Ah + (r0+8)*AST + kk + 2*qc + 8);
                al[0] = *(const uint32_t*)(Al + r0*AST + kk + 2*qc);
                al[1] = *(const uint32_t*)(Al + (r0+8)*AST + kk + 2*qc);
                al[2] = *(const uint32_t*)(Al + r0*AST + kk + 2*qc + 8);
                al[3] = *(const uint32_t*)(Al + (r0+8)*AST + kk + 2*qc + 8);
                #pragma unroll
                for (int nt = 0; nt < 16; nt++) {
                    const int cn = 8*nt + qr;
                    uint32_t bh0 = *(const uint32_t*)(Bh + cn*AST + kk + 2*qc);
                    uint32_t bh1 = *(const uint32_t*)(Bh + cn*AST + kk + 2*qc + 8);
                    uint32_t bl0 = *(const uint32_t*)(Bl + cn*AST + kk + 2*qc);
                    uint32_t bl1 = *(const uint32_t*)(Bl + cn*AST + kk + 2*qc + 8);
                    MMA_BF16(acc[nt], ah, bh0, bh1);
                    MMA_BF16(acc[nt], ah, bl0, bl1);
                    MMA_BF16(acc[nt], al, bh0, bh1);
                }
            }
            #pragma unroll 8
            for (int k = 0; k < KC; k++) {
                float a = __bfloat162float(Ah[erow*AST + k]) + __bfloat162float(Al[erow*AST + k]);
                accE += a * Es[ewhich*64 + k];
            }
        }
        const int r0 = 16*w + qr;
        #pragma unroll
        for (int nt = 0; nt < 16; nt++) {
            const int c0 = 8*nt + 2*qc;
            atomicAdd(&g_Mt[c0*HD + r0],         acc[nt][0]);
            atomicAdd(&g_Mt[(c0+1)*HD + r0],     acc[nt][1]);
            atomicAdd(&g_Mt[c0*HD + r0 + 8],     acc[nt][2]);
            atomicAdd(&g_Mt[(c0+1)*HD + r0 + 8], acc[nt][3]);
        }
        atomicAdd(ewhich ? &g_w0[erow] : &g_v[erow], accE);
    }
}

// ---------------- scan v4 (R13 math verbatim) + L2-prefetch clusters ----------------
// Cluster 0 (blocks 0..7): the recurrent scan, unchanged.
// Clusters 1..36 (blocks 8..295): stream fc2w (100 MB, fits L2) into L2 while
// the scan runs on 8 SMs, then exit. k_out then hits L2 instead of DRAM.
#define OFS_WI1 0
#define OFS_WH1 8192
#define OFS_WI2 16384
#define OFS_WH2 24576
#define OFS_MT  32768
#define OFS_U   49152
#define OFS_X   49408
#define OFS_XP  49536
#define OFS_H1  49664
#define OFS_H2  49920
#define OFS_G   50176
#define OFS_B1  50240
#define OFS_B2  50304
#define OFS_XB  50368
#define OFS_XB0 50496
#define OFS_C1  50624
#define OFS_C2  50640
#define SCAN_SMEM_FLOATS 50656
#define SCAN_SMEM_BYTES  (SCAN_SMEM_FLOATS*4)

__global__ void __launch_bounds__(256, 1) __cluster_dims__(CL, 1, 1)
k_scan(const float* __restrict__ h1_in, const float* __restrict__ c1_in,
       const float* __restrict__ h2_in, const float* __restrict__ c2_in,
       const float* __restrict__ fc1b,
       const float* __restrict__ wih1, const float* __restrict__ whh1,
       const float* __restrict__ bih1, const float* __restrict__ bhh1,
       const float* __restrict__ wih2, const float* __restrict__ whh2,
       const float* __restrict__ bih2, const float* __restrict__ bhh2,
       const float* __restrict__ fc2w,
       float* __restrict__ out, int out_size)
{
    if (blockIdx.x >= CL) {
        // ---- L2 prefetch of fc2w on otherwise-idle SMs ----
        const int nthr = (SCAN_GRID - CL) * 256;
        int idx = (blockIdx.x - CL) * 256 + threadIdx.x;
        const float4* p = (const float4*)fc2w;
        const int n4 = (NF*HD) / 4;
        float4 s = make_float4(0.f, 0.f, 0.f, 0.f);
        for (int i = idx; i < n4; i += nthr) {
            float4 v = __ldg(p + i);
            s.x += v.x; s.y += v.y; s.z += v.z; s.w += v.w;
        }
        if (__float_as_uint(s.x + s.y + s.z + s.w) == 0xDEADBEEFu)
            g_sink = s.x;   // never taken in practice; defeats DCE
        return;
    }

    extern __shared__ __align__(16) float sm[];
    const int tid  = threadIdx.x;
    const int warp = tid >> 5, lane = tid & 31;
    const uint32_t rank = ctarank();
    const uint32_t sbase = smem_u32(sm);

    for (int idx = tid; idx < 64*128; idx += 256) {
        int l = idx >> 7, k = idx & 127;
        int gr = ((l >> 4) << 7) + (int)rank*16 + (l & 15);
        sm[OFS_WI1 + idx] = wih1[gr*HD + k];
        sm[OFS_WH1 + idx] = whh1[gr*HD + k];
        sm[OFS_WI2 + idx] = wih2[gr*HD + k];
        sm[OFS_WH2 + idx] = whh2[gr*HD + k];
    }
    for (int idx = tid; idx < HD*HD; idx += 256) sm[OFS_MT + idx] = g_Mt[idx];
    if (tid < 64) {
        int gr = ((tid >> 4) << 7) + (int)rank*16 + (tid & 15);
        sm[OFS_B1 + tid] = bih1[gr] + bhh1[gr];
        sm[OFS_B2 + tid] = bih2[gr] + bhh2[gr];
    }
    if (tid < HD) {
        sm[OFS_XB  + tid] = fc1b[tid] + g_v[tid];
        sm[OFS_XB0 + tid] = fc1b[tid] + g_w0[tid];
        sm[OFS_U   + tid] = g_U[tid];
        sm[OFS_H1 + HD + tid] = h1_in[tid];
        sm[OFS_H2 + HD + tid] = h2_in[tid];
    }
    if (tid < 16) {
        int e = (int)rank*16 + tid;
        sm[OFS_C1 + tid] = c1_in[e];
        sm[OFS_C2 + tid] = c2_in[e];
    }
    __syncthreads();
    CLUSTER_BAR();

    for (int t = 0; t < S; t++) {
        const int p = t & 1;

        if (t == 0) {
            if (tid < HD) sm[OFS_X + tid] = fmaxf(sm[OFS_U + tid] + sm[OFS_XB0 + tid], 0.f);
            __syncthreads();
        } else {
            const int half = tid >> 7, h = tid & 127;
            const float* mt = sm + OFS_MT + half*64*HD;
            const float* hv = sm + OFS_H2 + (p^1)*HD + half*64;
            float a = 0.f;
            #pragma unroll 16
            for (int c = 0; c < 64; c++) a = fmaf(mt[c*HD + h], hv[c], a);
            sm[(half ? OFS_XP : OFS_X) + h] = a;
            __syncthreads();
            if (tid < HD)
                sm[OFS_X + tid] = fmaxf(sm[OFS_X + tid] + sm[OFS_XP + tid]
                                        + sm[OFS_U + p*HD + tid] + sm[OFS_XB + tid], 0.f);
            __syncthreads();
        }

        if (t < S-1 && tid < HD) sm[OFS_U + (p^1)*HD + tid] = g_U[(t+1)*HD + tid];

        {
            float4 xv = ((const float4*)(sm + OFS_X))[lane];
            float4 hv = ((const float4*)(sm + OFS_H1 + (p^1)*HD))[lane];
            #pragma unroll
            for (int i = 0; i < 8; i++) {
                int l = warp*8 + i;
                float4 wi = ((const float4*)(sm + OFS_WI1 + l*HD))[lane];
                float4 wh = ((const float4*)(sm + OFS_WH1 + l*HD))[lane];
                float pd = wi.x*xv.x + wi.y*xv.y + wi.z*xv.z + wi.w*xv.w
                         + wh.x*hv.x + wh.y*hv.y + wh.z*hv.z + wh.w*hv.w;
                #pragma unroll
                for (int off = 16; off; off >>= 1) pd += __shfl_xor_sync(0xffffffffu, pd, off);
                if (lane == 0) sm[OFS_G + l] = pd + sm[OFS_B1 + l];
            }
        }
        __syncthreads();
        if (tid < 16) {
            float gi = sm[OFS_G + tid],      gf = sm[OFS_G + 16 + tid];
            float gg = sm[OFS_G + 32 + tid], go = sm[OFS_G + 48 + tid];
            float c = sigm(gf)*sm[OFS_C1 + tid] + sigm(gi)*tanhf(gg);
            sm[OFS_C1 + tid] = c;
            sm[OFS_H1 + p*HD + (int)rank*16 + tid] = sigm(go)*tanhf(c);
        }
        __syncthreads();
        if (tid < 128) {
            int e = (int)rank*16 + (tid >> 3);
            st_cluster(mapa_u32(sbase + (uint32_t)(OFS_H1 + p*HD + e)*4u, (uint32_t)(tid & 7)),
                       sm[OFS_H1 + p*HD + e]);
        }
        CLUSTER_BAR();

        {
            float4 xv = ((const float4*)(sm + OFS_H1 + p*HD))[lane];
            float4 hv = ((const float4*)(sm + OFS_H2 + (p^1)*HD))[lane];
            #pragma unroll
            for (int i = 0; i < 8; i++) {
                int l = warp*8 + i;
                float4 wi = ((const float4*)(sm + OFS_WI2 + l*HD))[lane];
                float4 wh = ((const float4*)(sm + OFS_WH2 + l*HD))[lane];
                float pd = wi.x*xv.x + wi.y*xv.y + wi.z*xv.z + wi.w*xv.w
                         + wh.x*hv.x + wh.y*hv.y + wh.z*hv.z + wh.w*hv.w;
                #pragma unroll
                for (int off = 16; off; off >>= 1) pd += __shfl_xor_sync(0xffffffffu, pd, off);
                if (lane == 0) sm[OFS_G + l] = pd + sm[OFS_B2 + l];
            }
        }
        __syncthreads();
        if (tid < 16) {
            float gi = sm[OFS_G + tid],      gf = sm[OFS_G + 16 + tid];
            float gg = sm[OFS_G + 32 + tid], go = sm[OFS_G + 48 + tid];
            float c = sigm(gf)*sm[OFS_C2 + tid] + sigm(gi)*tanhf(gg);
            sm[OFS_C2 + tid] = c;
            float h = sigm(go)*tanhf(c);
            int e = (int)rank*16 + tid;
            sm[OFS_H2 + p*HD + e] = h;
            g_H2[t*HD + e] = h;
        }
        __syncthreads();
        if (tid < 128) {
            int e = (int)rank*16 + (tid >> 3);
            st_cluster(mapa_u32(sbase + (uint32_t)(OFS_H2 + p*HD + e)*4u, (uint32_t)(tid & 7)),
                       sm[OFS_H2 + p*HD + e]);
        }
        CLUSTER_BAR();
    }

    if (out_size >= S*NF + 4*HD && tid < 16) {
        int e = (int)rank*16 + tid;
        out[S*NF + 0*HD + e] = sm[OFS_H1 + HD + e];
        out[S*NF + 1*HD + e] = sm[OFS_C1 + tid];
        out[S*NF + 2*HD + e] = sm[OFS_H2 + HD + e];
        out[S*NF + 3*HD + e] = sm[OFS_C2 + tid];
    }
}

// ---------------- k_out v2 (R13 verbatim) ----------------
#define KO_SMEM ((2*128*AST + 2*64*AST)*2 + 512)
__global__ void __launch_bounds__(256, 4) k_out(const float* __restrict__ fc2w,
                                                const float* __restrict__ fc2b,
                                                const float* __restrict__ y,
                                                float* __restrict__ out) {
    extern __shared__ __align__(16) char smem_raw[];
    __nv_bfloat16* Ah = (__nv_bfloat16*)smem_raw;
    __nv_bfloat16* Al = Ah + 128*AST;
    __nv_bfloat16* Bh = Al + 128*AST;
    __nv_bfloat16* Bl = Bh + 64*AST;
    float* bs = (float*)(Bl + 64*AST);
    float* Cs = (float*)smem_raw;
    const int tid = threadIdx.x;
    const int w = tid >> 5, lane = tid & 31;
    const int qr = lane >> 2, qc = lane & 3;
    const int kg = blockIdx.x * 128;

    float acc[8][4];
    #pragma unroll
    for (int nt = 0; nt < 8; nt++)
        #pragma unroll
        for (int i = 0; i < 4; i++) acc[nt][i] = 0.f;

    if (tid < 128) bs[tid] = fc2b[kg + tid];

    for (int ck = 0; ck < 2; ck++) {
        const int ko = ck*64;
        __syncthreads();
        for (int i = tid; i < 128*32; i += 256) {
            int r = i >> 5, c2 = i & 31;
            float2 v = *(const float2*)(fc2w + (kg + r)*HD + ko + 2*c2);
            uint32_t h, l; split_bf2(v, h, l);
            *(uint32_t*)(Ah + r*AST + 2*c2) = h;
            *(uint32_t*)(Al + r*AST + 2*c2) = l;
        }
        for (int i = tid; i < 64*32; i += 256) {
            int tt = i >> 5, c2 = i & 31;
            float2 v = *(const float2*)(g_H2 + tt*HD + ko + 2*c2);
            uint32_t h, l; split_bf2(v, h, l);
            *(uint32_t*)(Bh + tt*AST + 2*c2) = h;
            *(uint32_t*)(Bl + tt*AST + 2*c2) = l;
        }
        __syncthreads();
        #pragma unroll
        for (int ks = 0; ks < 4; ks++) {
            const int kk = ks*16;
            const int r0 = 16*w + qr;
            uint32_t ah[4], al[4];
            ah[0] = *(const uint32_t*)(Ah + r0*AST + kk + 2*qc);
            ah[1] = *(const uint32_t*)(Ah + (r0+8)*AST + kk + 2*qc);
            ah[2] = *(const uint32_t*)(Ah + r0*AST + kk + 2*qc + 8);
            ah[3] = *(const uint32_t*)(Ah + (r0+8)*AST + kk + 2*qc + 8);
            al[0] = *(const uint32_t*)(Al + r0*AST + kk + 2*qc);
            al[1] = *(const uint32_t*)(Al + (r0+8)*AST + kk + 2*qc);
            al[2] = *(const uint32_t*)(Al + r0*AST + kk + 2*qc + 8);
            al[3] = *(const uint32_t*)(Al + (r0+8)*AST + kk + 2*qc + 8);
            #pragma unroll
            for (int nt = 0; nt < 8; nt++) {
                const int cn = 8*nt + qr;
                uint32_t bh0 = *(const uint32_t*)(Bh + cn*AST + kk + 2*qc);
                uint32_t bh1 = *(const uint32_t*)(Bh + cn*AST + kk + 2*qc + 8);
                uint32_t bl0 = *(const uint32_t*)(Bl + cn*AST + kk + 2*qc);
                uint32_t bl1 = *(const uint32_t*)(Bl + cn*AST + kk + 2*qc + 8);
                MMA_BF16(acc[nt], ah, bh0, bh1);
                MMA_BF16(acc[nt], ah, bl0, bl1);
                MMA_BF16(acc[nt], al, bh0, bh1);
            }
        }
    }
    __syncthreads();

    {
        const int r0 = 16*w + qr;
        #pragma unroll
        for (int nt = 0; nt < 8; nt++) {
            const int t0 = 8*nt + 2*qc;
            Cs[t0*132 + r0]           = acc[nt][0];
            Cs[(t0+1)*132 + r0]       = acc[nt][1];
            Cs[t0*132 + r0 + 8]       = acc[nt][2];
            Cs[(t0+1)*132 + r0 + 8]   = acc[nt][3];
        }
    }
    __syncthreads();

    for (int i = tid; i < 64*128; i += 256) {
        int tt = i >> 7, kk = i & 127;
        out[tt*NF + kg + kk] = Cs[tt*132 + kk] + bs[kk] + y[tt*NF + kg + kk];
    }
}

// ---------------- launcher ----------------
extern "C" void kernel_launch(void* const* d_in, const int* in_sizes, int n_in,
                              void* d_out, int out_size) {
    const float* z    = (const float*)d_in[0];
    const float* y    = (const float*)d_in[1];
    const float* pg0  = (const float*)d_in[2];
    const float* h1   = (const float*)d_in[3];
    const float* c1   = (const float*)d_in[4];
    const float* h2   = (const float*)d_in[5];
    const float* c2   = (const float*)d_in[6];
    const float* fc1w = (const float*)d_in[7];
    const float* fc1b = (const float*)d_in[8];
    const float* wih1 = (const float*)d_in[9];
    const float* whh1 = (const float*)d_in[10];
    const float* bih1 = (const float*)d_in[11];
    const float* bhh1 = (const float*)d_in[12];
    const float* wih2 = (const float*)d_in[13];
    const float* whh2 = (const float*)d_in[14];
    const float* bih2 = (const float*)d_in[15];
    const float* bhh2 = (const float*)d_in[16];
    const float* fc2w = (const float*)d_in[17];
    const float* fc2b = (const float*)d_in[18];
    float* out = (float*)d_out;

    cudaFuncSetAttribute(k_scan, cudaFuncAttributeMaxDynamicSharedMemorySize, SCAN_SMEM_BYTES);
    cudaFuncSetAttribute(k_gemm, cudaFuncAttributeMaxDynamicSharedMemorySize, GM_SMEM);
    cudaFuncSetAttribute(k_out,  cudaFuncAttributeMaxDynamicSharedMemorySize, KO_SMEM);

    k_zero<<<32, 256>>>();
    k_gemm<<<2*G_CTAS, 256, GM_SMEM>>>(fc1w, z, fc2w, fc2b, pg0);
    k_scan<<<SCAN_GRID, 256, SCAN_SMEM_BYTES>>>(h1, c1, h2, c2, fc1b,
                                                wih1, whh1, bih1, bhh1,
                                                wih2, whh2, bih2, bhh2,
                                                fc2w, out, out_size);
    k_out<<<NF/128, 256, KO_SMEM>>>(fc2w, fc2b, y, out);
}